// round 2
// baseline (speedup 1.0000x reference)
#include <cuda_runtime.h>
#include <cuda_fp16.h>

#define DINL __device__ __forceinline__

// ---------------- problem constants ----------------
constexpr int Bn = 4096;
constexpr int In = 512;
constexpr int Hn = 1024;
constexpr int Kd = Hn + In;      // 1536
constexpr int Nt = 8 * Hn;       // 8192  (8 gate-slices: f,i,c,o light then temp)

// ---------------- GEMM tiling (Ampere-style mma.sync path; tcgen05 is
// unavailable because the harness emits compute_103 PTX) ----------------
constexpr int BM = 128;
constexpr int BN = 128;
constexpr int BK = 64;                              // 128 bytes fp16 per row
constexpr int NK = Kd / BK;                         // 24
constexpr int STAGES = 4;
constexpr int STAGE_A = BM * BK * 2;                // 16384
constexpr int STAGE_B = BN * BK * 2;                // 16384
constexpr int STAGE_BYTES = STAGE_A + STAGE_B;      // 32768
constexpr int SMEM_TOTAL = STAGES * STAGE_BYTES;    // 131072

// ---------------- scratch (device globals; no allocations) ----------------
__device__ __align__(1024) __half g_A[2][(long)Bn * Kd];          // 25 MB
__device__ __align__(1024) __half g_W[(long)Nt * Kd];             // 25 MB
__device__ __align__(1024) __half g_Z[(long)Bn * Nt];             // 64 MB

// ---------------- PTX helpers (all legal on plain sm_103 target) ----------
DINL unsigned cvta_smem(const void* p) {
    unsigned a;
    asm("{ .reg .u64 t; cvta.to.shared.u64 t, %1; cvt.u32.u64 %0, t; }" : "=r"(a) : "l"(p));
    return a;
}
DINL void cp_async16(unsigned dst, const void* src) {
    asm volatile("cp.async.cg.shared.global [%0], [%1], 16;" :: "r"(dst), "l"(src));
}
DINL unsigned swz(unsigned o) { return o ^ ((o >> 3) & 0x70); }  // SW128

DINL void ldsm_x4(unsigned& r0, unsigned& r1, unsigned& r2, unsigned& r3, unsigned addr) {
    asm volatile("ldmatrix.sync.aligned.m8n8.x4.shared.b16 {%0,%1,%2,%3}, [%4];"
                 : "=r"(r0), "=r"(r1), "=r"(r2), "=r"(r3) : "r"(addr));
}
DINL void mma16816(float& d0, float& d1, float& d2, float& d3,
                   unsigned a0, unsigned a1, unsigned a2, unsigned a3,
                   unsigned b0, unsigned b1) {
    asm volatile(
        "mma.sync.aligned.m16n8k16.row.col.f32.f16.f16.f32 "
        "{%0,%1,%2,%3}, {%4,%5,%6,%7}, {%8,%9}, {%0,%1,%2,%3};"
        : "+f"(d0), "+f"(d1), "+f"(d2), "+f"(d3)
        : "r"(a0), "r"(a1), "r"(a2), "r"(a3), "r"(b0), "r"(b1));
}

// ---------------- convert kernels ----------------
__global__ void convert_a(const float* __restrict__ y,
                          const float* __restrict__ hl,
                          const float* __restrict__ ht) {
    const int total = 2 * Bn * (Kd / 8);
    for (int idx = blockIdx.x * blockDim.x + threadIdx.x; idx < total;
         idx += gridDim.x * blockDim.x) {
        const int br  = idx / (Bn * (Kd / 8));
        const int rem = idx - br * (Bn * (Kd / 8));
        const int m   = rem / (Kd / 8);
        const int k   = (rem % (Kd / 8)) * 8;
        const float* src;
        if (k < Hn) src = (br ? ht : hl) + (long)m * Hn + k;
        else        src = y + (long)m * In + (k - Hn);
        float4 a = reinterpret_cast<const float4*>(src)[0];
        float4 b = reinterpret_cast<const float4*>(src)[1];
        __half2 h0 = __floats2half2_rn(a.x, a.y);
        __half2 h1 = __floats2half2_rn(a.z, a.w);
        __half2 h2 = __floats2half2_rn(b.x, b.y);
        __half2 h3 = __floats2half2_rn(b.z, b.w);
        uint4 v = make_uint4(*(unsigned*)&h0, *(unsigned*)&h1,
                             *(unsigned*)&h2, *(unsigned*)&h3);
        *reinterpret_cast<uint4*>(&g_A[br][(long)m * Kd + k]) = v;
    }
}

__global__ void convert_w(const float* __restrict__ w0, const float* __restrict__ w1,
                          const float* __restrict__ w2, const float* __restrict__ w3,
                          const float* __restrict__ w4, const float* __restrict__ w5,
                          const float* __restrict__ w6, const float* __restrict__ w7) {
    const int total = Nt * (Kd / 8);
    for (int idx = blockIdx.x * blockDim.x + threadIdx.x; idx < total;
         idx += gridDim.x * blockDim.x) {
        const int n = idx / (Kd / 8);
        const int k = (idx % (Kd / 8)) * 8;
        const int s = n >> 10;
        const int j = n & 1023;
        const float* wp = (s == 0) ? w0 : (s == 1) ? w1 : (s == 2) ? w2 : (s == 3) ? w3
                        : (s == 4) ? w4 : (s == 5) ? w5 : (s == 6) ? w6 : w7;
        const float* src = wp + (long)j * Kd + k;
        float4 a = reinterpret_cast<const float4*>(src)[0];
        float4 b = reinterpret_cast<const float4*>(src)[1];
        __half2 h0 = __floats2half2_rn(a.x, a.y);
        __half2 h1 = __floats2half2_rn(a.z, a.w);
        __half2 h2 = __floats2half2_rn(b.x, b.y);
        __half2 h3 = __floats2half2_rn(b.z, b.w);
        uint4 v = make_uint4(*(unsigned*)&h0, *(unsigned*)&h1,
                             *(unsigned*)&h2, *(unsigned*)&h3);
        *reinterpret_cast<uint4*>(&g_W[(long)n * Kd + k]) = v;
    }
}

// ---------------- GEMM ----------------
DINL void load_stage(unsigned sb, unsigned tid, const __half* __restrict__ Ag,
                     const __half* __restrict__ Bg, int m0, int n0, int s, int kt) {
    const int k0 = kt * BK;
    const unsigned sA = sb + s * STAGE_BYTES;
    const unsigned sB = sA + STAGE_A;
#pragma unroll
    for (int i = 0; i < 4; i++) {                 // A: 128 rows x 8 x 16B
        unsigned idx = i * 256 + tid;
        unsigned r = idx >> 3, c = idx & 7;
        cp_async16(sA + swz(r * 128 + c * 16), Ag + (long)(m0 + r) * Kd + k0 + c * 8);
    }
#pragma unroll
    for (int i = 0; i < 4; i++) {                 // B: 128 rows x 8 x 16B
        unsigned idx = i * 256 + tid;
        unsigned r = idx >> 3, c = idx & 7;
        cp_async16(sB + swz(r * 128 + c * 16), Bg + (long)(n0 + r) * Kd + k0 + c * 8);
    }
    asm volatile("cp.async.commit_group;" ::: "memory");
}

__global__ void __launch_bounds__(256, 1) gemm_kernel() {
    extern __shared__ char smem[];
    const unsigned tid  = threadIdx.x;
    const unsigned wid  = tid >> 5;
    const unsigned lane = tid & 31;
    const unsigned sb   = cvta_smem(smem);
    const unsigned wm   = wid & 3;        // 4 warps along M -> 32 rows each
    const unsigned wn   = wid >> 2;       // 2 warps along N -> 64 cols each
    const int n0 = blockIdx.x * BN;
    const int m0 = blockIdx.y * BM;
    const __half* __restrict__ Ag = g_A[blockIdx.x >> 5];   // branch = n0/4096
    const __half* __restrict__ Bg = g_W;

    // prologue: fill STAGES-1 stages
    load_stage(sb, tid, Ag, Bg, m0, n0, 0, 0);
    load_stage(sb, tid, Ag, Bg, m0, n0, 1, 1);
    load_stage(sb, tid, Ag, Bg, m0, n0, 2, 2);

    float acc[2][8][4];
#pragma unroll
    for (int mt = 0; mt < 2; mt++)
#pragma unroll
        for (int nt = 0; nt < 8; nt++)
#pragma unroll
            for (int q = 0; q < 4; q++) acc[mt][nt][q] = 0.0f;

    // lane -> ldmatrix row address components
    const unsigned lrow  = lane & 15;            // row within 16
    const unsigned lkoff = (lane >> 4) << 3;     // 0 or 8 halves in K

    for (int kt = 0; kt < NK; kt++) {
        asm volatile("cp.async.wait_group 2;" ::: "memory");
        __syncthreads();
        const unsigned sA = sb + (kt % STAGES) * STAGE_BYTES;
        const unsigned sB = sA + STAGE_A;

#pragma unroll
        for (int kk = 0; kk < 4; kk++) {
            const unsigned kb = (kk * 16 + lkoff) * 2;    // byte offset in K
            unsigned a[2][4], b[4][4];
#pragma unroll
            for (int mt = 0; mt < 2; mt++) {
                unsigned row = wm * 32 + mt * 16 + lrow;
                ldsm_x4(a[mt][0], a[mt][1], a[mt][2], a[mt][3], sA + swz(row * 128 + kb));
            }
#pragma unroll
            for (int nt16 = 0; nt16 < 4; nt16++) {
                unsigned row = wn * 64 + nt16 * 16 + lrow;
                ldsm_x4(b[nt16][0], b[nt16][1], b[nt16][2], b[nt16][3], sB + swz(row * 128 + kb));
            }
#pragma unroll
            for (int mt = 0; mt < 2; mt++)
#pragma unroll
                for (int nt = 0; nt < 8; nt++) {
                    const int g = nt >> 1, h = nt & 1;
                    mma16816(acc[mt][nt][0], acc[mt][nt][1], acc[mt][nt][2], acc[mt][nt][3],
                             a[mt][0], a[mt][1], a[mt][2], a[mt][3],
                             b[g][h], b[g][2 + h]);
                }
        }
        if (kt + STAGES - 1 < NK)
            load_stage(sb, tid, Ag, Bg, m0, n0, (kt + STAGES - 1) % STAGES, kt + STAGES - 1);
        else
            asm volatile("cp.async.commit_group;" ::: "memory");  // keep group count uniform
    }

    // epilogue: accum -> fp16 z
    const int grp = lane >> 2;            // row within 8
    const int thr = lane & 3;             // 2-col group
#pragma unroll
    for (int mt = 0; mt < 2; mt++) {
        const long row0 = (long)m0 + wm * 32 + mt * 16 + grp;
#pragma unroll
        for (int nt = 0; nt < 8; nt++) {
            const long col = (long)n0 + wn * 64 + nt * 8 + thr * 2;
            __half2 lo = __floats2half2_rn(acc[mt][nt][0], acc[mt][nt][1]);
            __half2 hi = __floats2half2_rn(acc[mt][nt][2], acc[mt][nt][3]);
            *reinterpret_cast<__half2*>(&g_Z[row0 * Nt + col])       = lo;
            *reinterpret_cast<__half2*>(&g_Z[(row0 + 8) * Nt + col]) = hi;
        }
    }
}

// ---------------- elementwise epilogue ----------------
DINL float sigf(float x) { return 1.0f / (1.0f + __expf(-x)); }

__global__ void lstm_ep(const float* __restrict__ cl,
                        const float* __restrict__ b0, const float* __restrict__ b1,
                        const float* __restrict__ b2, const float* __restrict__ b3,
                        const float* __restrict__ b4, const float* __restrict__ b5,
                        const float* __restrict__ b6, const float* __restrict__ b7,
                        float* __restrict__ out) {
    const int t = blockIdx.x * blockDim.x + threadIdx.x;
    if (t >= Bn * (Hn / 2)) return;
    const int m = t / (Hn / 2);
    const int j = (t % (Hn / 2)) * 2;
    const __half* z = g_Z + (long)m * Nt + j;

    float2 zf1 = __half22float2(*(const __half2*)(z + 0 * Hn));
    float2 zi1 = __half22float2(*(const __half2*)(z + 1 * Hn));
    float2 zc1 = __half22float2(*(const __half2*)(z + 2 * Hn));
    float2 zo1 = __half22float2(*(const __half2*)(z + 3 * Hn));
    float2 zf2 = __half22float2(*(const __half2*)(z + 4 * Hn));
    float2 zi2 = __half22float2(*(const __half2*)(z + 5 * Hn));
    float2 zc2 = __half22float2(*(const __half2*)(z + 6 * Hn));
    float2 zo2 = __half22float2(*(const __half2*)(z + 7 * Hn));

    float2 v;
    v = *(const float2*)(b0 + j); zf1.x += v.x; zf1.y += v.y;
    v = *(const float2*)(b1 + j); zi1.x += v.x; zi1.y += v.y;
    v = *(const float2*)(b2 + j); zc1.x += v.x; zc1.y += v.y;
    v = *(const float2*)(b3 + j); zo1.x += v.x; zo1.y += v.y;
    v = *(const float2*)(b4 + j); zf2.x += v.x; zf2.y += v.y;
    v = *(const float2*)(b5 + j); zi2.x += v.x; zi2.y += v.y;
    v = *(const float2*)(b6 + j); zc2.x += v.x; zc2.y += v.y;
    v = *(const float2*)(b7 + j); zo2.x += v.x; zo2.y += v.y;

    float2 c = *(const float2*)(cl + (long)m * Hn + j);

    float2 cn, hn;
    {
        float f1 = sigf(zf1.x), i1 = sigf(zi1.x), ch1 = tanhf(zc1.x), o1 = sigf(zo1.x);
        float f2 = sigf(zf2.x), i2 = sigf(zi2.x), ch2 = tanhf(zc2.x), o2 = sigf(zo2.x);
        cn.x = (f1 * c.x + i1 * ch1) + (f2 * c.x + i2 * ch2);
        hn.x = (o1 + o2) * tanhf(cn.x);
    }
    {
        float f1 = sigf(zf1.y), i1 = sigf(zi1.y), ch1 = tanhf(zc1.y), o1 = sigf(zo1.y);
        float f2 = sigf(zf2.y), i2 = sigf(zi2.y), ch2 = tanhf(zc2.y), o2 = sigf(zo2.y);
        cn.y = (f1 * c.y + i1 * ch1) + (f2 * c.y + i2 * ch2);
        hn.y = (o1 + o2) * tanhf(cn.y);
    }

    *(float2*)(out + (long)m * Hn + j) = hn;
    *(float2*)(out + (long)Bn * Hn + (long)m * Hn + j) = cn;
}

// ---------------- launch ----------------
extern "C" void kernel_launch(void* const* d_in, const int* in_sizes, int n_in,
                              void* d_out, int out_size) {
    const float* y  = (const float*)d_in[0];
    const float* hl = (const float*)d_in[1];
    const float* cl = (const float*)d_in[2];
    const float* ht = (const float*)d_in[3];
    // d_in[4] = c_temp (unused by the reference math)
    const float* w0 = (const float*)d_in[5];
    const float* w1 = (const float*)d_in[7];
    const float* w2 = (const float*)d_in[9];
    const float* w3 = (const float*)d_in[11];
    const float* w4 = (const float*)d_in[13];
    const float* w5 = (const float*)d_in[15];
    const float* w6 = (const float*)d_in[17];
    const float* w7 = (const float*)d_in[19];
    const float* b0 = (const float*)d_in[6];
    const float* b1 = (const float*)d_in[8];
    const float* b2 = (const float*)d_in[10];
    const float* b3 = (const float*)d_in[12];
    const float* b4 = (const float*)d_in[14];
    const float* b5 = (const float*)d_in[16];
    const float* b6 = (const float*)d_in[18];
    const float* b7 = (const float*)d_in[20];
    float* out = (float*)d_out;

    cudaFuncSetAttribute(gemm_kernel, cudaFuncAttributeMaxDynamicSharedMemorySize, SMEM_TOTAL);

    convert_a<<<1024, 256>>>(y, hl, ht);
    convert_w<<<1024, 256>>>(w0, w1, w2, w3, w4, w5, w6, w7);
    gemm_kernel<<<dim3(Nt / BN, Bn / BM), 256, SMEM_TOTAL>>>();
    lstm_ep<<<(Bn * (Hn / 2) + 255) / 256, 256>>>(cl, b0, b1, b2, b3, b4, b5, b6, b7, out);
}

// round 3
// speedup vs baseline: 1.0678x; 1.0678x over previous
#include <cuda_runtime.h>
#include <cuda_fp16.h>

#define DINL __device__ __forceinline__

// ---------------- problem constants ----------------
constexpr int Bn = 4096;
constexpr int In = 512;
constexpr int Hn = 1024;
constexpr int Kd = Hn + In;      // 1536
constexpr int Nt = 8 * Hn;       // 8192  (8 gate-slices: f,i,c,o light then temp)

// ---------------- GEMM tiling (Ampere-style mma.sync path; tcgen05 is
// unavailable because the harness emits compute_103 PTX) ----------------
constexpr int BM = 128;
constexpr int BN = 256;
constexpr int BK = 64;                              // 128 bytes fp16 per row
constexpr int NK = Kd / BK;                         // 24
constexpr int STAGES = 4;
constexpr int STAGE_A = BM * BK * 2;                // 16384
constexpr int STAGE_B = BN * BK * 2;                // 32768
constexpr int STAGE_BYTES = STAGE_A + STAGE_B;      // 49152
constexpr int SMEM_TOTAL = STAGES * STAGE_BYTES;    // 196608

// ---------------- scratch (device globals; no allocations) ----------------
__device__ __align__(1024) __half g_A[2][(long)Bn * Kd];          // 25 MB
__device__ __align__(1024) __half g_W[(long)Nt * Kd];             // 25 MB
__device__ __align__(1024) __half g_Z[(long)Bn * Nt];             // 64 MB

// ---------------- PTX helpers (all legal on plain sm_103 target) ----------
DINL unsigned cvta_smem(const void* p) {
    unsigned a;
    asm("{ .reg .u64 t; cvta.to.shared.u64 t, %1; cvt.u32.u64 %0, t; }" : "=r"(a) : "l"(p));
    return a;
}
DINL void cp_async16(unsigned dst, const void* src) {
    asm volatile("cp.async.cg.shared.global [%0], [%1], 16;" :: "r"(dst), "l"(src));
}
DINL unsigned swz(unsigned o) { return o ^ ((o >> 3) & 0x70); }  // SW128

DINL void ldsm_x4(unsigned& r0, unsigned& r1, unsigned& r2, unsigned& r3, unsigned addr) {
    asm volatile("ldmatrix.sync.aligned.m8n8.x4.shared.b16 {%0,%1,%2,%3}, [%4];"
                 : "=r"(r0), "=r"(r1), "=r"(r2), "=r"(r3) : "r"(addr));
}
DINL void mma16816(float& d0, float& d1, float& d2, float& d3,
                   unsigned a0, unsigned a1, unsigned a2, unsigned a3,
                   unsigned b0, unsigned b1) {
    asm volatile(
        "mma.sync.aligned.m16n8k16.row.col.f32.f16.f16.f32 "
        "{%0,%1,%2,%3}, {%4,%5,%6,%7}, {%8,%9}, {%0,%1,%2,%3};"
        : "+f"(d0), "+f"(d1), "+f"(d2), "+f"(d3)
        : "r"(a0), "r"(a1), "r"(a2), "r"(a3), "r"(b0), "r"(b1));
}
DINL float htanh(float x) {
    float r;
    asm("tanh.approx.f32 %0, %1;" : "=f"(r) : "f"(x));
    return r;
}

// ---------------- convert kernels ----------------
__global__ void convert_a(const float* __restrict__ y,
                          const float* __restrict__ hl,
                          const float* __restrict__ ht) {
    const int total = 2 * Bn * (Kd / 8);
    for (int idx = blockIdx.x * blockDim.x + threadIdx.x; idx < total;
         idx += gridDim.x * blockDim.x) {
        const int br  = idx / (Bn * (Kd / 8));
        const int rem = idx - br * (Bn * (Kd / 8));
        const int m   = rem / (Kd / 8);
        const int k   = (rem % (Kd / 8)) * 8;
        const float* src;
        if (k < Hn) src = (br ? ht : hl) + (long)m * Hn + k;
        else        src = y + (long)m * In + (k - Hn);
        float4 a = reinterpret_cast<const float4*>(src)[0];
        float4 b = reinterpret_cast<const float4*>(src)[1];
        __half2 h0 = __floats2half2_rn(a.x, a.y);
        __half2 h1 = __floats2half2_rn(a.z, a.w);
        __half2 h2 = __floats2half2_rn(b.x, b.y);
        __half2 h3 = __floats2half2_rn(b.z, b.w);
        uint4 v = make_uint4(*(unsigned*)&h0, *(unsigned*)&h1,
                             *(unsigned*)&h2, *(unsigned*)&h3);
        *reinterpret_cast<uint4*>(&g_A[br][(long)m * Kd + k]) = v;
    }
}

__global__ void convert_w(const float* __restrict__ w0, const float* __restrict__ w1,
                          const float* __restrict__ w2, const float* __restrict__ w3,
                          const float* __restrict__ w4, const float* __restrict__ w5,
                          const float* __restrict__ w6, const float* __restrict__ w7) {
    const int total = Nt * (Kd / 8);
    for (int idx = blockIdx.x * blockDim.x + threadIdx.x; idx < total;
         idx += gridDim.x * blockDim.x) {
        const int n = idx / (Kd / 8);
        const int k = (idx % (Kd / 8)) * 8;
        const int s = n >> 10;
        const int j = n & 1023;
        const float* wp = (s == 0) ? w0 : (s == 1) ? w1 : (s == 2) ? w2 : (s == 3) ? w3
                        : (s == 4) ? w4 : (s == 5) ? w5 : (s == 6) ? w6 : w7;
        const float* src = wp + (long)j * Kd + k;
        float4 a = reinterpret_cast<const float4*>(src)[0];
        float4 b = reinterpret_cast<const float4*>(src)[1];
        __half2 h0 = __floats2half2_rn(a.x, a.y);
        __half2 h1 = __floats2half2_rn(a.z, a.w);
        __half2 h2 = __floats2half2_rn(b.x, b.y);
        __half2 h3 = __floats2half2_rn(b.z, b.w);
        uint4 v = make_uint4(*(unsigned*)&h0, *(unsigned*)&h1,
                             *(unsigned*)&h2, *(unsigned*)&h3);
        *reinterpret_cast<uint4*>(&g_W[(long)n * Kd + k]) = v;
    }
}

// ---------------- GEMM ----------------
DINL void load_stage(unsigned sb, unsigned tid, const __half* __restrict__ Ag,
                     const __half* __restrict__ Bg, int m0, int n0, int s, int kt) {
    const int k0 = kt * BK;
    const unsigned sA = sb + s * STAGE_BYTES;
    const unsigned sB = sA + STAGE_A;
#pragma unroll
    for (int i = 0; i < 4; i++) {                 // A: 128 rows x 8 x 16B
        unsigned idx = i * 256 + tid;
        unsigned r = idx >> 3, c = idx & 7;
        cp_async16(sA + swz(r * 128 + c * 16), Ag + (long)(m0 + r) * Kd + k0 + c * 8);
    }
#pragma unroll
    for (int i = 0; i < 8; i++) {                 // B: 256 rows x 8 x 16B
        unsigned idx = i * 256 + tid;
        unsigned r = idx >> 3, c = idx & 7;
        cp_async16(sB + swz(r * 128 + c * 16), Bg + (long)(n0 + r) * Kd + k0 + c * 8);
    }
    asm volatile("cp.async.commit_group;" ::: "memory");
}

__global__ void __launch_bounds__(256, 1) gemm_kernel() {
    extern __shared__ char smem[];
    const unsigned tid  = threadIdx.x;
    const unsigned wid  = tid >> 5;
    const unsigned lane = tid & 31;
    const unsigned sb   = cvta_smem(smem);
    const unsigned wm   = wid & 1;        // 2 warps along M -> 64 rows each
    const unsigned wn   = wid >> 1;       // 4 warps along N -> 64 cols each
    const int n0 = blockIdx.x * BN;
    const int m0 = blockIdx.y * BM;
    const __half* __restrict__ Ag = g_A[blockIdx.x >> 4];   // branch = n0/4096
    const __half* __restrict__ Bg = g_W;

    // prologue: fill STAGES-1 stages
    load_stage(sb, tid, Ag, Bg, m0, n0, 0, 0);
    load_stage(sb, tid, Ag, Bg, m0, n0, 1, 1);
    load_stage(sb, tid, Ag, Bg, m0, n0, 2, 2);

    float acc[4][8][4];
#pragma unroll
    for (int mt = 0; mt < 4; mt++)
#pragma unroll
        for (int nt = 0; nt < 8; nt++)
#pragma unroll
            for (int q = 0; q < 4; q++) acc[mt][nt][q] = 0.0f;

    // lane -> ldmatrix row address components
    const unsigned lrow  = lane & 15;            // row within 16
    const unsigned lkoff = (lane >> 4) << 3;     // 0 or 8 halves in K

    for (int kt = 0; kt < NK; kt++) {
        asm volatile("cp.async.wait_group 2;" ::: "memory");
        __syncthreads();
        const unsigned sA = sb + (kt % STAGES) * STAGE_BYTES;
        const unsigned sB = sA + STAGE_A;

#pragma unroll
        for (int kk = 0; kk < 4; kk++) {
            const unsigned kb = (kk * 16 + lkoff) * 2;    // byte offset in K
            unsigned a[4][4], b[4][4];
#pragma unroll
            for (int mt = 0; mt < 4; mt++) {
                unsigned row = wm * 64 + mt * 16 + lrow;
                ldsm_x4(a[mt][0], a[mt][1], a[mt][2], a[mt][3], sA + swz(row * 128 + kb));
            }
#pragma unroll
            for (int nt16 = 0; nt16 < 4; nt16++) {
                unsigned row = wn * 64 + nt16 * 16 + lrow;
                ldsm_x4(b[nt16][0], b[nt16][1], b[nt16][2], b[nt16][3], sB + swz(row * 128 + kb));
            }
#pragma unroll
            for (int mt = 0; mt < 4; mt++)
#pragma unroll
                for (int nt = 0; nt < 8; nt++) {
                    const int g = nt >> 1, h = nt & 1;
                    mma16816(acc[mt][nt][0], acc[mt][nt][1], acc[mt][nt][2], acc[mt][nt][3],
                             a[mt][0], a[mt][1], a[mt][2], a[mt][3],
                             b[g][h], b[g][2 + h]);
                }
        }
        if (kt + STAGES - 1 < NK)
            load_stage(sb, tid, Ag, Bg, m0, n0, (kt + STAGES - 1) % STAGES, kt + STAGES - 1);
        else
            asm volatile("cp.async.commit_group;" ::: "memory");  // keep group count uniform
    }

    // epilogue: accum -> fp16 z
    const int grp = lane >> 2;            // row within 8
    const int thr = lane & 3;             // 2-col group
#pragma unroll
    for (int mt = 0; mt < 4; mt++) {
        const long row0 = (long)m0 + wm * 64 + mt * 16 + grp;
#pragma unroll
        for (int nt = 0; nt < 8; nt++) {
            const long col = (long)n0 + wn * 64 + nt * 8 + thr * 2;
            __half2 lo = __floats2half2_rn(acc[mt][nt][0], acc[mt][nt][1]);
            __half2 hi = __floats2half2_rn(acc[mt][nt][2], acc[mt][nt][3]);
            *reinterpret_cast<__half2*>(&g_Z[row0 * Nt + col])       = lo;
            *reinterpret_cast<__half2*>(&g_Z[(row0 + 8) * Nt + col]) = hi;
        }
    }
}

// ---------------- elementwise epilogue ----------------
DINL float sigf(float x) { return 1.0f / (1.0f + __expf(-x)); }

__global__ void lstm_ep(const float* __restrict__ cl,
                        const float* __restrict__ b0, const float* __restrict__ b1,
                        const float* __restrict__ b2, const float* __restrict__ b3,
                        const float* __restrict__ b4, const float* __restrict__ b5,
                        const float* __restrict__ b6, const float* __restrict__ b7,
                        float* __restrict__ out) {
    const int t = blockIdx.x * blockDim.x + threadIdx.x;
    if (t >= Bn * (Hn / 2)) return;
    const int m = t / (Hn / 2);
    const int j = (t % (Hn / 2)) * 2;
    const __half* z = g_Z + (long)m * Nt + j;

    float2 zf1 = __half22float2(*(const __half2*)(z + 0 * Hn));
    float2 zi1 = __half22float2(*(const __half2*)(z + 1 * Hn));
    float2 zc1 = __half22float2(*(const __half2*)(z + 2 * Hn));
    float2 zo1 = __half22float2(*(const __half2*)(z + 3 * Hn));
    float2 zf2 = __half22float2(*(const __half2*)(z + 4 * Hn));
    float2 zi2 = __half22float2(*(const __half2*)(z + 5 * Hn));
    float2 zc2 = __half22float2(*(const __half2*)(z + 6 * Hn));
    float2 zo2 = __half22float2(*(const __half2*)(z + 7 * Hn));

    float2 v;
    v = *(const float2*)(b0 + j); zf1.x += v.x; zf1.y += v.y;
    v = *(const float2*)(b1 + j); zi1.x += v.x; zi1.y += v.y;
    v = *(const float2*)(b2 + j); zc1.x += v.x; zc1.y += v.y;
    v = *(const float2*)(b3 + j); zo1.x += v.x; zo1.y += v.y;
    v = *(const float2*)(b4 + j); zf2.x += v.x; zf2.y += v.y;
    v = *(const float2*)(b5 + j); zi2.x += v.x; zi2.y += v.y;
    v = *(const float2*)(b6 + j); zc2.x += v.x; zc2.y += v.y;
    v = *(const float2*)(b7 + j); zo2.x += v.x; zo2.y += v.y;

    float2 c = *(const float2*)(cl + (long)m * Hn + j);

    float2 cn, hn;
    {
        float f1 = sigf(zf1.x), i1 = sigf(zi1.x), ch1 = htanh(zc1.x), o1 = sigf(zo1.x);
        float f2 = sigf(zf2.x), i2 = sigf(zi2.x), ch2 = htanh(zc2.x), o2 = sigf(zo2.x);
        cn.x = (f1 * c.x + i1 * ch1) + (f2 * c.x + i2 * ch2);
        hn.x = (o1 + o2) * htanh(cn.x);
    }
    {
        float f1 = sigf(zf1.y), i1 = sigf(zi1.y), ch1 = htanh(zc1.y), o1 = sigf(zo1.y);
        float f2 = sigf(zf2.y), i2 = sigf(zi2.y), ch2 = htanh(zc2.y), o2 = sigf(zo2.y);
        cn.y = (f1 * c.y + i1 * ch1) + (f2 * c.y + i2 * ch2);
        hn.y = (o1 + o2) * htanh(cn.y);
    }

    *(float2*)(out + (long)m * Hn + j) = hn;
    *(float2*)(out + (long)Bn * Hn + (long)m * Hn + j) = cn;
}

// ---------------- launch ----------------
extern "C" void kernel_launch(void* const* d_in, const int* in_sizes, int n_in,
                              void* d_out, int out_size) {
    const float* y  = (const float*)d_in[0];
    const float* hl = (const float*)d_in[1];
    const float* cl = (const float*)d_in[2];
    const float* ht = (const float*)d_in[3];
    // d_in[4] = c_temp (unused by the reference math)
    const float* w0 = (const float*)d_in[5];
    const float* w1 = (const float*)d_in[7];
    const float* w2 = (const float*)d_in[9];
    const float* w3 = (const float*)d_in[11];
    const float* w4 = (const float*)d_in[13];
    const float* w5 = (const float*)d_in[15];
    const float* w6 = (const float*)d_in[17];
    const float* w7 = (const float*)d_in[19];
    const float* b0 = (const float*)d_in[6];
    const float* b1 = (const float*)d_in[8];
    const float* b2 = (const float*)d_in[10];
    const float* b3 = (const float*)d_in[12];
    const float* b4 = (const float*)d_in[14];
    const float* b5 = (const float*)d_in[16];
    const float* b6 = (const float*)d_in[18];
    const float* b7 = (const float*)d_in[20];
    float* out = (float*)d_out;

    cudaFuncSetAttribute(gemm_kernel, cudaFuncAttributeMaxDynamicSharedMemorySize, SMEM_TOTAL);

    convert_a<<<1024, 256>>>(y, hl, ht);
    convert_w<<<1024, 256>>>(w0, w1, w2, w3, w4, w5, w6, w7);
    gemm_kernel<<<dim3(Nt / BN, Bn / BM), 256, SMEM_TOTAL>>>();
    lstm_ep<<<(Bn * (Hn / 2) + 255) / 256, 256>>>(cl, b0, b1, b2, b3, b4, b5, b6, b7, out);
}

// round 4
// speedup vs baseline: 1.1138x; 1.0431x over previous
#include <cuda_runtime.h>
#include <cuda_fp16.h>

#define DINL __device__ __forceinline__

// ---------------- problem constants ----------------
constexpr int Bn = 4096;
constexpr int In = 512;
constexpr int Hn = 1024;
constexpr int Kd = Hn + In;      // 1536
constexpr int Nt = 8 * Hn;       // 8192  (8 gate-slices: f,i,c,o light then temp)

// ---------------- GEMM tiling (Ampere-style mma.sync path; tcgen05 is
// unavailable because the harness emits compute_103 PTX) ----------------
// 2 CTAs/SM: 96 KB SMEM each, <=128 regs/thread.
constexpr int BM = 128;
constexpr int BN = 128;
constexpr int BK = 64;                              // 128 bytes fp16 per row
constexpr int NK = Kd / BK;                         // 24
constexpr int STAGES = 3;
constexpr int STAGE_A = BM * BK * 2;                // 16384
constexpr int STAGE_B = BN * BK * 2;                // 16384
constexpr int STAGE_BYTES = STAGE_A + STAGE_B;      // 32768
constexpr int SMEM_TOTAL = STAGES * STAGE_BYTES;    // 98304

// ---------------- scratch (device globals; no allocations) ----------------
__device__ __align__(1024) __half g_A[2][(long)Bn * Kd];          // 25 MB
__device__ __align__(1024) __half g_W[(long)Nt * Kd];             // 25 MB
__device__ __align__(1024) __half g_Z[(long)Bn * Nt];             // 64 MB

// ---------------- PTX helpers (all legal on plain sm_103 target) ----------
DINL unsigned cvta_smem(const void* p) {
    unsigned a;
    asm("{ .reg .u64 t; cvta.to.shared.u64 t, %1; cvt.u32.u64 %0, t; }" : "=r"(a) : "l"(p));
    return a;
}
DINL void cp_async16(unsigned dst, const void* src) {
    asm volatile("cp.async.cg.shared.global [%0], [%1], 16;" :: "r"(dst), "l"(src));
}
DINL unsigned swz(unsigned o) { return o ^ ((o >> 3) & 0x70); }  // SW128

DINL void ldsm_x4(unsigned& r0, unsigned& r1, unsigned& r2, unsigned& r3, unsigned addr) {
    asm volatile("ldmatrix.sync.aligned.m8n8.x4.shared.b16 {%0,%1,%2,%3}, [%4];"
                 : "=r"(r0), "=r"(r1), "=r"(r2), "=r"(r3) : "r"(addr));
}
DINL void mma16816(float& d0, float& d1, float& d2, float& d3,
                   unsigned a0, unsigned a1, unsigned a2, unsigned a3,
                   unsigned b0, unsigned b1) {
    asm volatile(
        "mma.sync.aligned.m16n8k16.row.col.f32.f16.f16.f32 "
        "{%0,%1,%2,%3}, {%4,%5,%6,%7}, {%8,%9}, {%0,%1,%2,%3};"
        : "+f"(d0), "+f"(d1), "+f"(d2), "+f"(d3)
        : "r"(a0), "r"(a1), "r"(a2), "r"(a3), "r"(b0), "r"(b1));
}
DINL float htanh(float x) {
    float r;
    asm("tanh.approx.f32 %0, %1;" : "=f"(r) : "f"(x));
    return r;
}

// ---------------- convert kernels ----------------
__global__ void convert_a(const float* __restrict__ y,
                          const float* __restrict__ hl,
                          const float* __restrict__ ht) {
    const int total = 2 * Bn * (Kd / 8);
    for (int idx = blockIdx.x * blockDim.x + threadIdx.x; idx < total;
         idx += gridDim.x * blockDim.x) {
        const int br  = idx / (Bn * (Kd / 8));
        const int rem = idx - br * (Bn * (Kd / 8));
        const int m   = rem / (Kd / 8);
        const int k   = (rem % (Kd / 8)) * 8;
        const float* src;
        if (k < Hn) src = (br ? ht : hl) + (long)m * Hn + k;
        else        src = y + (long)m * In + (k - Hn);
        float4 a = reinterpret_cast<const float4*>(src)[0];
        float4 b = reinterpret_cast<const float4*>(src)[1];
        __half2 h0 = __floats2half2_rn(a.x, a.y);
        __half2 h1 = __floats2half2_rn(a.z, a.w);
        __half2 h2 = __floats2half2_rn(b.x, b.y);
        __half2 h3 = __floats2half2_rn(b.z, b.w);
        uint4 v = make_uint4(*(unsigned*)&h0, *(unsigned*)&h1,
                             *(unsigned*)&h2, *(unsigned*)&h3);
        *reinterpret_cast<uint4*>(&g_A[br][(long)m * Kd + k]) = v;
    }
}

__global__ void convert_w(const float* __restrict__ w0, const float* __restrict__ w1,
                          const float* __restrict__ w2, const float* __restrict__ w3,
                          const float* __restrict__ w4, const float* __restrict__ w5,
                          const float* __restrict__ w6, const float* __restrict__ w7) {
    const int total = Nt * (Kd / 8);
    for (int idx = blockIdx.x * blockDim.x + threadIdx.x; idx < total;
         idx += gridDim.x * blockDim.x) {
        const int n = idx / (Kd / 8);
        const int k = (idx % (Kd / 8)) * 8;
        const int s = n >> 10;
        const int j = n & 1023;
        const float* wp = (s == 0) ? w0 : (s == 1) ? w1 : (s == 2) ? w2 : (s == 3) ? w3
                        : (s == 4) ? w4 : (s == 5) ? w5 : (s == 6) ? w6 : w7;
        const float* src = wp + (long)j * Kd + k;
        float4 a = reinterpret_cast<const float4*>(src)[0];
        float4 b = reinterpret_cast<const float4*>(src)[1];
        __half2 h0 = __floats2half2_rn(a.x, a.y);
        __half2 h1 = __floats2half2_rn(a.z, a.w);
        __half2 h2 = __floats2half2_rn(b.x, b.y);
        __half2 h3 = __floats2half2_rn(b.z, b.w);
        uint4 v = make_uint4(*(unsigned*)&h0, *(unsigned*)&h1,
                             *(unsigned*)&h2, *(unsigned*)&h3);
        *reinterpret_cast<uint4*>(&g_W[(long)n * Kd + k]) = v;
    }
}

// ---------------- GEMM ----------------
DINL void load_stage(unsigned sb, unsigned tid, const __half* __restrict__ Ag,
                     const __half* __restrict__ Bg, int m0, int n0, int s, int kt) {
    const int k0 = kt * BK;
    const unsigned sA = sb + s * STAGE_BYTES;
    const unsigned sB = sA + STAGE_A;
#pragma unroll
    for (int i = 0; i < 4; i++) {                 // A: 128 rows x 8 x 16B
        unsigned idx = i * 256 + tid;
        unsigned r = idx >> 3, c = idx & 7;
        cp_async16(sA + swz(r * 128 + c * 16), Ag + (long)(m0 + r) * Kd + k0 + c * 8);
    }
#pragma unroll
    for (int i = 0; i < 4; i++) {                 // B: 128 rows x 8 x 16B
        unsigned idx = i * 256 + tid;
        unsigned r = idx >> 3, c = idx & 7;
        cp_async16(sB + swz(r * 128 + c * 16), Bg + (long)(n0 + r) * Kd + k0 + c * 8);
    }
    asm volatile("cp.async.commit_group;" ::: "memory");
}

__global__ void __launch_bounds__(256, 2) gemm_kernel() {
    extern __shared__ char smem[];
    const unsigned tid  = threadIdx.x;
    const unsigned wid  = tid >> 5;
    const unsigned lane = tid & 31;
    const unsigned sb   = cvta_smem(smem);
    const unsigned wm   = wid & 3;        // 4 warps along M -> 32 rows each
    const unsigned wn   = wid >> 2;       // 2 warps along N -> 64 cols each
    const int n0 = blockIdx.x * BN;
    const int m0 = blockIdx.y * BM;
    const __half* __restrict__ Ag = g_A[blockIdx.x >> 5];   // branch = n0/4096
    const __half* __restrict__ Bg = g_W;

    // prologue: fill STAGES-1 stages
    load_stage(sb, tid, Ag, Bg, m0, n0, 0, 0);
    load_stage(sb, tid, Ag, Bg, m0, n0, 1, 1);

    float acc[2][8][4];
#pragma unroll
    for (int mt = 0; mt < 2; mt++)
#pragma unroll
        for (int nt = 0; nt < 8; nt++)
#pragma unroll
            for (int q = 0; q < 4; q++) acc[mt][nt][q] = 0.0f;

    // lane -> ldmatrix row address components
    const unsigned lrow  = lane & 15;            // row within 16
    const unsigned lkoff = (lane >> 4) << 3;     // 0 or 8 halves in K

    for (int kt = 0; kt < NK; kt++) {
        asm volatile("cp.async.wait_group 1;" ::: "memory");
        __syncthreads();
        const unsigned sA = sb + (kt % STAGES) * STAGE_BYTES;
        const unsigned sB = sA + STAGE_A;

#pragma unroll
        for (int kk = 0; kk < 4; kk++) {
            const unsigned kb = (kk * 16 + lkoff) * 2;    // byte offset in K
            unsigned a[2][4], b[4][4];
#pragma unroll
            for (int mt = 0; mt < 2; mt++) {
                unsigned row = wm * 32 + mt * 16 + lrow;
                ldsm_x4(a[mt][0], a[mt][1], a[mt][2], a[mt][3], sA + swz(row * 128 + kb));
            }
#pragma unroll
            for (int nt16 = 0; nt16 < 4; nt16++) {
                unsigned row = wn * 64 + nt16 * 16 + lrow;
                ldsm_x4(b[nt16][0], b[nt16][1], b[nt16][2], b[nt16][3], sB + swz(row * 128 + kb));
            }
#pragma unroll
            for (int mt = 0; mt < 2; mt++)
#pragma unroll
                for (int nt = 0; nt < 8; nt++) {
                    const int g = nt >> 1, h = nt & 1;
                    mma16816(acc[mt][nt][0], acc[mt][nt][1], acc[mt][nt][2], acc[mt][nt][3],
                             a[mt][0], a[mt][1], a[mt][2], a[mt][3],
                             b[g][h], b[g][2 + h]);
                }
        }
        if (kt + STAGES - 1 < NK)
            load_stage(sb, tid, Ag, Bg, m0, n0, (kt + STAGES - 1) % STAGES, kt + STAGES - 1);
        else
            asm volatile("cp.async.commit_group;" ::: "memory");  // keep group count uniform
    }

    // epilogue: accum -> fp16 z
    const int grp = lane >> 2;            // row within 8
    const int thr = lane & 3;             // 2-col group
#pragma unroll
    for (int mt = 0; mt < 2; mt++) {
        const long row0 = (long)m0 + wm * 32 + mt * 16 + grp;
#pragma unroll
        for (int nt = 0; nt < 8; nt++) {
            const long col = (long)n0 + wn * 64 + nt * 8 + thr * 2;
            __half2 lo = __floats2half2_rn(acc[mt][nt][0], acc[mt][nt][1]);
            __half2 hi = __floats2half2_rn(acc[mt][nt][2], acc[mt][nt][3]);
            *reinterpret_cast<__half2*>(&g_Z[row0 * Nt + col])       = lo;
            *reinterpret_cast<__half2*>(&g_Z[(row0 + 8) * Nt + col]) = hi;
        }
    }
}

// ---------------- elementwise epilogue ----------------
// sigmoid(x) = 0.5*tanh(x/2) + 0.5   (tanh.approx: abs err ~1e-4, well in budget)
DINL float sigf(float x) { return fmaf(htanh(x * 0.5f), 0.5f, 0.5f); }

__global__ void lstm_ep(const float* __restrict__ cl,
                        const float* __restrict__ b0, const float* __restrict__ b1,
                        const float* __restrict__ b2, const float* __restrict__ b3,
                        const float* __restrict__ b4, const float* __restrict__ b5,
                        const float* __restrict__ b6, const float* __restrict__ b7,
                        float* __restrict__ out) {
    const int t = blockIdx.x * blockDim.x + threadIdx.x;
    if (t >= Bn * (Hn / 2)) return;
    const int m = t / (Hn / 2);
    const int j = (t % (Hn / 2)) * 2;
    const __half* z = g_Z + (long)m * Nt + j;

    float2 zf1 = __half22float2(*(const __half2*)(z + 0 * Hn));
    float2 zi1 = __half22float2(*(const __half2*)(z + 1 * Hn));
    float2 zc1 = __half22float2(*(const __half2*)(z + 2 * Hn));
    float2 zo1 = __half22float2(*(const __half2*)(z + 3 * Hn));
    float2 zf2 = __half22float2(*(const __half2*)(z + 4 * Hn));
    float2 zi2 = __half22float2(*(const __half2*)(z + 5 * Hn));
    float2 zc2 = __half22float2(*(const __half2*)(z + 6 * Hn));
    float2 zo2 = __half22float2(*(const __half2*)(z + 7 * Hn));

    float2 v;
    v = *(const float2*)(b0 + j); zf1.x += v.x; zf1.y += v.y;
    v = *(const float2*)(b1 + j); zi1.x += v.x; zi1.y += v.y;
    v = *(const float2*)(b2 + j); zc1.x += v.x; zc1.y += v.y;
    v = *(const float2*)(b3 + j); zo1.x += v.x; zo1.y += v.y;
    v = *(const float2*)(b4 + j); zf2.x += v.x; zf2.y += v.y;
    v = *(const float2*)(b5 + j); zi2.x += v.x; zi2.y += v.y;
    v = *(const float2*)(b6 + j); zc2.x += v.x; zc2.y += v.y;
    v = *(const float2*)(b7 + j); zo2.x += v.x; zo2.y += v.y;

    float2 c = *(const float2*)(cl + (long)m * Hn + j);

    float2 cn, hn;
    {
        float f1 = sigf(zf1.x), i1 = sigf(zi1.x), ch1 = htanh(zc1.x), o1 = sigf(zo1.x);
        float f2 = sigf(zf2.x), i2 = sigf(zi2.x), ch2 = htanh(zc2.x), o2 = sigf(zo2.x);
        cn.x = (f1 * c.x + i1 * ch1) + (f2 * c.x + i2 * ch2);
        hn.x = (o1 + o2) * htanh(cn.x);
    }
    {
        float f1 = sigf(zf1.y), i1 = sigf(zi1.y), ch1 = htanh(zc1.y), o1 = sigf(zo1.y);
        float f2 = sigf(zf2.y), i2 = sigf(zi2.y), ch2 = htanh(zc2.y), o2 = sigf(zo2.y);
        cn.y = (f1 * c.y + i1 * ch1) + (f2 * c.y + i2 * ch2);
        hn.y = (o1 + o2) * htanh(cn.y);
    }

    *(float2*)(out + (long)m * Hn + j) = hn;
    *(float2*)(out + (long)Bn * Hn + (long)m * Hn + j) = cn;
}

// ---------------- launch ----------------
extern "C" void kernel_launch(void* const* d_in, const int* in_sizes, int n_in,
                              void* d_out, int out_size) {
    const float* y  = (const float*)d_in[0];
    const float* hl = (const float*)d_in[1];
    const float* cl = (const float*)d_in[2];
    const float* ht = (const float*)d_in[3];
    // d_in[4] = c_temp (unused by the reference math)
    const float* w0 = (const float*)d_in[5];
    const float* w1 = (const float*)d_in[7];
    const float* w2 = (const float*)d_in[9];
    const float* w3 = (const float*)d_in[11];
    const float* w4 = (const float*)d_in[13];
    const float* w5 = (const float*)d_in[15];
    const float* w6 = (const float*)d_in[17];
    const float* w7 = (const float*)d_in[19];
    const float* b0 = (const float*)d_in[6];
    const float* b1 = (const float*)d_in[8];
    const float* b2 = (const float*)d_in[10];
    const float* b3 = (const float*)d_in[12];
    const float* b4 = (const float*)d_in[14];
    const float* b5 = (const float*)d_in[16];
    const float* b6 = (const float*)d_in[18];
    const float* b7 = (const float*)d_in[20];
    float* out = (float*)d_out;

    cudaFuncSetAttribute(gemm_kernel, cudaFuncAttributeMaxDynamicSharedMemorySize, SMEM_TOTAL);

    convert_a<<<1024, 256>>>(y, hl, ht);
    convert_w<<<1024, 256>>>(w0, w1, w2, w3, w4, w5, w6, w7);
    gemm_kernel<<<dim3(Nt / BN, Bn / BM), 256, SMEM_TOTAL>>>();
    lstm_ep<<<(Bn * (Hn / 2) + 255) / 256, 256>>>(cl, b0, b1, b2, b3, b4, b5, b6, b7, out);
}